// round 8
// baseline (speedup 1.0000x reference)
#include <cuda_runtime.h>
#include <math.h>
#include <stdint.h>

typedef unsigned long long ull;
typedef unsigned int uint;

// ---------------- scratch (no allocations allowed) ----------------
// g_hc[b][chunk][8192]: per 64-j chunk, interleaved tf32 hi/lo layout:
//   float index = kt*1024 + c*16 + q*4 + sub,  j = 8*kt + q (+4 if subbit)
//   sub: 0 = hi(j), 1 = hi(j+4), 2 = lo(j), 3 = lo(j+4)
__device__ float g_hc[16 * 32 * 8192];    // 16.8 MB
__device__ float g_ssrc[16 * 2048];
__device__ float g_sdst[16 * 2048];

// ---------------- helpers ----------------
__device__ __forceinline__ ull pack2(float lo, float hi) {
    ull r; asm("mov.b64 %0, {%1, %2};" : "=l"(r) : "f"(lo), "f"(hi)); return r;
}
__device__ __forceinline__ void unpack2(ull v, float& lo, float& hi) {
    asm("mov.b64 {%0, %1}, %2;" : "=f"(lo), "=f"(hi) : "l"(v));
}
__device__ __forceinline__ ull fma2(ull a, ull b, ull c) {
    ull d; asm("fma.rn.f32x2 %0, %1, %2, %3;" : "=l"(d) : "l"(a), "l"(b), "l"(c)); return d;
}
__device__ __forceinline__ float rna_tf32(float x) {
    float r; asm("cvt.rna.tf32.f32 %0, %1;" : "=f"(r) : "f"(x)); return r;
}

// m16n8k8 tf32 mma, D/C fp32 (target-neutral PTX, works at sm_103)
#define MMA_TF32(d, A0, A1, A2, A3, B0, B1)                                   \
    asm volatile("mma.sync.aligned.m16n8k8.row.col.f32.tf32.tf32.f32 "        \
        "{%0,%1,%2,%3}, {%4,%5,%6,%7}, {%8,%9}, {%0,%1,%2,%3};"               \
        : "+f"((d)[0]), "+f"((d)[1]), "+f"((d)[2]), "+f"((d)[3])              \
        : "r"(A0), "r"(A1), "r"(A2), "r"(A3), "r"(B0), "r"(B1))

// ================================================================
// Kernel A: h = x @ W ; emits g_hc (chunk-interleaved tf32 hi/lo),
// g_ssrc, g_sdst. One block = 64 rows = exactly one (b, chunk).
// ================================================================
__global__ void __launch_bounds__(256, 1) gemm_h_kernel(const float* __restrict__ x,
                                                        const float* __restrict__ W,
                                                        const float* __restrict__ w2) {
    extern __shared__ float dynsm[];
    float* ws = dynsm;            // [256][64]
    float* xs = dynsm + 16384;    // [64][256]

    const int t    = threadIdx.x;
    const int rowg = t >> 4;
    const int cg   = t & 15;
    const long base_row = (long)blockIdx.x * 64;

    {
        const float4* wg  = (const float4*)W;
        float4*       ws4 = (float4*)ws;
        #pragma unroll
        for (int i = 0; i < 16; i++) ws4[t + i * 256] = wg[t + i * 256];
        const float4* xg  = (const float4*)(x + base_row * 256);
        float4*       xs4 = (float4*)xs;
        #pragma unroll
        for (int i = 0; i < 16; i++) xs4[t + i * 256] = xg[t + i * 256];
    }
    __syncthreads();

    ull acc2[4][2];
    #pragma unroll
    for (int r = 0; r < 4; r++) { acc2[r][0] = 0ULL; acc2[r][1] = 0ULL; }

    #pragma unroll 8
    for (int k = 0; k < 256; k++) {
        const ulonglong2 wv = *(const ulonglong2*)&ws[k * 64 + cg * 4];
        #pragma unroll
        for (int r = 0; r < 4; r++) {
            const float xv = xs[(rowg * 4 + r) * 256 + k];
            const ull x2 = pack2(xv, xv);
            acc2[r][0] = fma2(wv.x, x2, acc2[r][0]);
            acc2[r][1] = fma2(wv.y, x2, acc2[r][1]);
        }
    }

    float av[4][4];
    const float4 as = *(const float4*)(w2 + cg * 4);
    const float4 ad = *(const float4*)(w2 + 64 + cg * 4);
    #pragma unroll
    for (int r = 0; r < 4; r++) {
        unpack2(acc2[r][0], av[r][0], av[r][1]);
        unpack2(acc2[r][1], av[r][2], av[r][3]);
        float ps = av[r][0] * as.x + av[r][1] * as.y + av[r][2] * as.z + av[r][3] * as.w;
        float pd = av[r][0] * ad.x + av[r][1] * ad.y + av[r][2] * ad.z + av[r][3] * ad.w;
        #pragma unroll
        for (int o = 1; o < 16; o <<= 1) {
            ps += __shfl_xor_sync(0xffffffffu, ps, o);
            pd += __shfl_xor_sync(0xffffffffu, pd, o);
        }
        if (cg == 0) {
            g_ssrc[base_row + rowg * 4 + r] = ps;
            g_sdst[base_row + rowg * 4 + r] = pd;
        }
    }

    // stage h into smem, then emit chunk-interleaved hi/lo to g_hc
    __syncthreads();              // k-loop readers of ws/xs done
    float* h_sm = dynsm;          // [64][65]
    #pragma unroll
    for (int r = 0; r < 4; r++)
        #pragma unroll
        for (int u = 0; u < 4; u++)
            h_sm[(rowg * 4 + r) * 65 + cg * 4 + u] = av[r][u];
    __syncthreads();

    const int b  = (int)(base_row >> 11);
    const int ck = (int)((base_row & 2047) >> 6);
    float* dst = g_hc + ((long)b * 32 + ck) * 8192;
    // 2048 float4 pieces total (kt 0..7 x c 0..63 x q 0..3): 8 iterations.
    // (Round-7 bug: only 4 iterations -> j 32..63 half of H was garbage.)
    #pragma unroll
    for (int it = 0; it < 8; it++) {
        const int f4 = t + it * 256;       // 0..2047
        const int kt = f4 >> 8;
        const int c  = (f4 >> 2) & 63;
        const int q  = f4 & 3;
        const int j  = kt * 8 + q;
        const float hA = h_sm[j * 65 + c];
        const float hB = h_sm[(j + 4) * 65 + c];
        const float hiA = rna_tf32(hA), loA = rna_tf32(hA - hiA);
        const float hiB = rna_tf32(hB), loB = rna_tf32(hB - hiB);
        *(float4*)(dst + f4 * 4) = make_float4(hiA, hiB, loA, loB);
    }
}

// ================================================================
// Kernel B: masked softmax + P@V on tensor cores (mma.sync tf32).
// CTA = 256 rows of one batch, 256 threads, 8 warps x 32 rows.
// Per 64-j chunk:
//   stage H (coalesced copy into interleaved hs layout),
//   score (each warp its 32 rows; p~ = tf32(exp(relu)) or 0 -> psm),
//   mma: 2 row-tiles x 8 n-tiles x 8 k-tiles x (hi+lo) per warp;
//        B-quad {b0h,b1h,b0l,b1l} = one conflict-free LDS.128.
// l summed from the same p~ the MMA consumes; no online max
// (scores = relu(..) <= ~40, exp can't overflow fp32).
// ================================================================
__global__ void __launch_bounds__(256, 1) attn_kernel(const int* __restrict__ adj,
                                                      float* __restrict__ out) {
    extern __shared__ float sm[];
    float* psm = sm;                 // [256][68]  conflict-free A-frag reads
    float* hs  = sm + 256 * 68;      // [8192]     interleaved H chunk
    float* lsm = hs + 8192;          // [256]      row sums

    const int t  = threadIdx.x;
    const int ln = t & 31;
    const int w  = t >> 5;
    const int b  = blockIdx.y;
    const int ib = blockIdx.x * 256;
    const long bn = (long)b * 2048;
    const int R0 = w * 32;           // warp row base

    // score-phase decomposition: thread covers rows rh+2i (i=0..15), j's u*4..+3
    const int u  = ln & 15;
    const int rh = ln >> 4;

    float ssrcv[16];
    #pragma unroll
    for (int i = 0; i < 16; i++)
        ssrcv[i] = g_ssrc[bn + ib + R0 + rh + 2 * i];

    const int* adjp = adj + (bn + ib + R0 + rh) * 2048 + u * 4;
    const float* hsrc = g_hc + (long)b * 32 * 8192;

    float acc[2][8][4];
    #pragma unroll
    for (int tl = 0; tl < 2; tl++)
        #pragma unroll
        for (int nt = 0; nt < 8; nt++)
            #pragma unroll
            for (int e = 0; e < 4; e++) acc[tl][nt][e] = 0.f;
    float lpart[16];
    #pragma unroll
    for (int i = 0; i < 16; i++) lpart[i] = 0.f;

    const int q  = ln & 3;           // mma-phase lane decomposition
    const int r4 = ln >> 2;

    for (int ck = 0; ck < 32; ck++) {
        const int jc = ck * 64;
        __syncthreads();             // prev chunk's mma readers done
        // ---- stage H: pure coalesced copy, linear STS (conflict-free) ----
        {
            const float4* src = (const float4*)(hsrc + (long)ck * 8192);
            float4*       dst = (float4*)hs;
            #pragma unroll
            for (int it = 0; it < 8; it++) dst[t + it * 256] = src[t + it * 256];
        }
        // ---- score phase ----
        const float4 sd = *((const float4*)(g_sdst + bn + jc) + u);
        #pragma unroll
        for (int i = 0; i < 16; i++) {
            const int4 a = *(const int4*)(adjp + (long)(2 * i) * 2048 + jc);
            const float p0 = (a.x > 0) ? rna_tf32(__expf(fmaxf(ssrcv[i] + sd.x, 0.f))) : 0.f;
            const float p1 = (a.y > 0) ? rna_tf32(__expf(fmaxf(ssrcv[i] + sd.y, 0.f))) : 0.f;
            const float p2 = (a.z > 0) ? rna_tf32(__expf(fmaxf(ssrcv[i] + sd.z, 0.f))) : 0.f;
            const float p3 = (a.w > 0) ? rna_tf32(__expf(fmaxf(ssrcv[i] + sd.w, 0.f))) : 0.f;
            lpart[i] += (p0 + p1) + (p2 + p3);
            *(float4*)&psm[(R0 + rh + 2 * i) * 68 + u * 4] = make_float4(p0, p1, p2, p3);
        }
        __syncthreads();             // hs + psm visible
        // ---- mma phase: 2 tiles x 8 nt x 8 kt x (hi+lo) ----
        #pragma unroll
        for (int kt = 0; kt < 8; kt++) {
            const int pcol = kt * 8 + q;
            uint A0[2], A1[2], A2[2], A3[2];
            #pragma unroll
            for (int tl = 0; tl < 2; tl++) {
                const int rb = R0 + tl * 16 + r4;
                A0[tl] = __float_as_uint(psm[rb * 68 + pcol]);
                A1[tl] = __float_as_uint(psm[(rb + 8) * 68 + pcol]);
                A2[tl] = __float_as_uint(psm[rb * 68 + pcol + 4]);
                A3[tl] = __float_as_uint(psm[(rb + 8) * 68 + pcol + 4]);
            }
            #pragma unroll
            for (int nt = 0; nt < 8; nt++) {
                const int c = nt * 8 + r4;
                const float4 bq = *(const float4*)&hs[kt * 1024 + c * 16 + q * 4];
                const uint b0h = __float_as_uint(bq.x), b1h = __float_as_uint(bq.y);
                const uint b0l = __float_as_uint(bq.z), b1l = __float_as_uint(bq.w);
                MMA_TF32(acc[0][nt], A0[0], A1[0], A2[0], A3[0], b0h, b1h);
                MMA_TF32(acc[1][nt], A0[1], A1[1], A2[1], A3[1], b0h, b1h);
                MMA_TF32(acc[0][nt], A0[0], A1[0], A2[0], A3[0], b0l, b1l);
                MMA_TF32(acc[1][nt], A0[1], A1[1], A2[1], A3[1], b0l, b1l);
            }
        }
    }

    // ---- l: reduce over the 16 u-lanes of each parity half ----
    #pragma unroll
    for (int o = 1; o < 16; o <<= 1)
        #pragma unroll
        for (int i = 0; i < 16; i++)
            lpart[i] += __shfl_xor_sync(0xffffffffu, lpart[i], o);
    if (ln == 0) {
        #pragma unroll
        for (int i = 0; i < 16; i++) lsm[R0 + 2 * i] = lpart[i];
    } else if (ln == 16) {
        #pragma unroll
        for (int i = 0; i < 16; i++) lsm[R0 + 2 * i + 1] = lpart[i];
    }
    __syncwarp();

    // ---- epilogue: divide by l, store ----
    #pragma unroll
    for (int tl = 0; tl < 2; tl++) {
        const float inv0 = 1.f / lsm[R0 + tl * 16 + r4];
        const float inv1 = 1.f / lsm[R0 + tl * 16 + r4 + 8];
        const long row0 = bn + ib + R0 + tl * 16 + r4;
        #pragma unroll
        for (int nt = 0; nt < 8; nt++) {
            *(float2*)(out + row0 * 64 + nt * 8 + 2 * q) =
                make_float2(acc[tl][nt][0] * inv0, acc[tl][nt][1] * inv0);
            *(float2*)(out + (row0 + 8) * 64 + nt * 8 + 2 * q) =
                make_float2(acc[tl][nt][2] * inv1, acc[tl][nt][3] * inv1);
        }
    }
}

// ================================================================
// launch
// inputs: x f32[16,2048,256], adj i32[16,2048,2048],
//         weight f32[256,64], weight2 f32[128,1]
// output: f32[16,2048,64]
// ================================================================
extern "C" void kernel_launch(void* const* d_in, const int* in_sizes, int n_in,
                              void* d_out, int out_size) {
    const float* x   = (const float*)d_in[0];
    const int*   adj = (const int*)d_in[1];
    const float* W   = (const float*)d_in[2];
    const float* w2  = (const float*)d_in[3];
    float* out = (float*)d_out;

    cudaFuncSetAttribute(gemm_h_kernel,
                         cudaFuncAttributeMaxDynamicSharedMemorySize, 131072);
    cudaFuncSetAttribute(attn_kernel,
                         cudaFuncAttributeMaxDynamicSharedMemorySize, 103424);

    gemm_h_kernel<<<512, 256, 131072>>>(x, W, w2);     // 64 rows = one (b, chunk)
    attn_kernel<<<dim3(8, 16), 256, 103424>>>(adj, out);  // 8 i-tiles x 16 batches
}

// round 9
// speedup vs baseline: 1.6547x; 1.6547x over previous
#include <cuda_runtime.h>
#include <math.h>
#include <stdint.h>

typedef unsigned long long ull;
typedef unsigned int uint;

// ---------------- scratch (no allocations allowed) ----------------
// g_hc[b][chunk][8192]: per 64-j chunk, interleaved tf32 hi/lo layout:
//   float index = kt*1024 + c*16 + q*4 + sub,  j = 8*kt + q (+4 if sub&1)
//   sub: 0 = hi(j), 1 = hi(j+4), 2 = lo(j), 3 = lo(j+4)
__device__ float g_hc[16 * 32 * 8192];    // 16.8 MB
__device__ float g_ssrc[16 * 2048];
__device__ float g_sdst[16 * 2048];

// ---------------- helpers ----------------
__device__ __forceinline__ uint smem_u32(const void* p) {
    uint a;
    asm("{ .reg .u64 t; cvta.to.shared.u64 t, %1; cvt.u32.u64 %0, t; }" : "=r"(a) : "l"(p));
    return a;
}
__device__ __forceinline__ ull pack2(float lo, float hi) {
    ull r; asm("mov.b64 %0, {%1, %2};" : "=l"(r) : "f"(lo), "f"(hi)); return r;
}
__device__ __forceinline__ void unpack2(ull v, float& lo, float& hi) {
    asm("mov.b64 {%0, %1}, %2;" : "=f"(lo), "=f"(hi) : "l"(v));
}
__device__ __forceinline__ ull fma2(ull a, ull b, ull c) {
    ull d; asm("fma.rn.f32x2 %0, %1, %2, %3;" : "=l"(d) : "l"(a), "l"(b), "l"(c)); return d;
}
__device__ __forceinline__ float rna_tf32(float x) {
    float r; asm("cvt.rna.tf32.f32 %0, %1;" : "=f"(r) : "f"(x)); return r;
}
__device__ __forceinline__ void cpasync16(uint dst, const void* src) {
    asm volatile("cp.async.cg.shared.global [%0], [%1], 16;" :: "r"(dst), "l"(src));
}

// m16n8k8 tf32 mma, D/C fp32 (target-neutral PTX, works at sm_103)
#define MMA_TF32(d, A0, A1, A2, A3, B0, B1)                                   \
    asm volatile("mma.sync.aligned.m16n8k8.row.col.f32.tf32.tf32.f32 "        \
        "{%0,%1,%2,%3}, {%4,%5,%6,%7}, {%8,%9}, {%0,%1,%2,%3};"               \
        : "+f"((d)[0]), "+f"((d)[1]), "+f"((d)[2]), "+f"((d)[3])              \
        : "r"(A0), "r"(A1), "r"(A2), "r"(A3), "r"(B0), "r"(B1))

// ================================================================
// Kernel A: h = x @ W ; emits g_hc (chunk-interleaved tf32 hi/lo),
// g_ssrc, g_sdst. Block = 32 rows, 256 threads, 96KB smem -> 2 CTA/SM.
// ================================================================
__global__ void __launch_bounds__(256, 2) gemm_h_kernel(const float* __restrict__ x,
                                                        const float* __restrict__ W,
                                                        const float* __restrict__ w2) {
    extern __shared__ float dynsm[];
    float* ws = dynsm;            // [256][64]  = 64KB
    float* xs = dynsm + 16384;    // [32][256]  = 32KB

    const int t    = threadIdx.x;
    const int rowg = t >> 4;      // 0..15 -> 2 rows each
    const int cg   = t & 15;      // 4 cols
    const long base_row = (long)blockIdx.x * 32;

    {
        const float4* wg  = (const float4*)W;
        float4*       ws4 = (float4*)ws;
        #pragma unroll
        for (int i = 0; i < 16; i++) ws4[t + i * 256] = wg[t + i * 256];
        const float4* xg  = (const float4*)(x + base_row * 256);
        float4*       xs4 = (float4*)xs;
        #pragma unroll
        for (int i = 0; i < 8; i++) xs4[t + i * 256] = xg[t + i * 256];
    }
    __syncthreads();

    ull acc2[2][2];
    #pragma unroll
    for (int r = 0; r < 2; r++) { acc2[r][0] = 0ULL; acc2[r][1] = 0ULL; }

    #pragma unroll 8
    for (int k = 0; k < 256; k++) {
        const ulonglong2 wv = *(const ulonglong2*)&ws[k * 64 + cg * 4];
        #pragma unroll
        for (int r = 0; r < 2; r++) {
            const float xv = xs[(rowg * 2 + r) * 256 + k];
            const ull x2 = pack2(xv, xv);
            acc2[r][0] = fma2(wv.x, x2, acc2[r][0]);
            acc2[r][1] = fma2(wv.y, x2, acc2[r][1]);
        }
    }

    float av[2][4];
    const float4 as = *(const float4*)(w2 + cg * 4);
    const float4 ad = *(const float4*)(w2 + 64 + cg * 4);
    #pragma unroll
    for (int r = 0; r < 2; r++) {
        unpack2(acc2[r][0], av[r][0], av[r][1]);
        unpack2(acc2[r][1], av[r][2], av[r][3]);
        float ps = av[r][0] * as.x + av[r][1] * as.y + av[r][2] * as.z + av[r][3] * as.w;
        float pd = av[r][0] * ad.x + av[r][1] * ad.y + av[r][2] * ad.z + av[r][3] * ad.w;
        #pragma unroll
        for (int o = 1; o < 16; o <<= 1) {
            ps += __shfl_xor_sync(0xffffffffu, ps, o);
            pd += __shfl_xor_sync(0xffffffffu, pd, o);
        }
        if (cg == 0) {
            g_ssrc[base_row + rowg * 2 + r] = ps;
            g_sdst[base_row + rowg * 2 + r] = pd;
        }
    }

    // stage h rows (local 0..31) into smem, then emit interleaved hi/lo
    __syncthreads();              // k-loop readers of ws/xs done
    float* h_sm = dynsm;          // [32][65]
    #pragma unroll
    for (int r = 0; r < 2; r++)
        #pragma unroll
        for (int u = 0; u < 4; u++)
            h_sm[(rowg * 2 + r) * 65 + cg * 4 + u] = av[r][u];
    __syncthreads();

    const int b     = (int)(base_row >> 11);
    const int ck    = (int)((base_row & 2047) >> 6);
    const int jhalf = (int)((base_row >> 5) & 1);   // which 32-j half of chunk
    float* dst = g_hc + ((long)b * 32 + ck) * 8192;
    // this block covers kt_global = jhalf*4 .. +3 (1024 float4 pieces)
    #pragma unroll
    for (int it = 0; it < 4; it++) {
        const int f4l = t + it * 256;        // 0..1023
        const int ktl = f4l >> 8;            // 0..3
        const int c   = (f4l >> 2) & 63;
        const int q   = f4l & 3;
        const int jl  = ktl * 8 + q;         // local row 0..27
        const float hA = h_sm[jl * 65 + c];
        const float hB = h_sm[(jl + 4) * 65 + c];
        const float hiA = rna_tf32(hA), loA = rna_tf32(hA - hiA);
        const float hiB = rna_tf32(hB), loB = rna_tf32(hB - hiB);
        const int f4g = (jhalf * 4 + ktl) * 256 + c * 4 + q;
        *(float4*)(dst + f4g * 4) = make_float4(hiA, hiB, loA, loB);
    }
}

// ================================================================
// Kernel B: masked softmax + P@V on tensor cores (mma.sync tf32).
// CTA = 128 rows, 256 threads, 8 warps x 16 rows; 2 CTAs/SM.
// H chunks double-buffered via cp.async (overlaps with score+mma).
// Per chunk: score (p~ = tf32(exp(relu)) or 0 -> psm, l += p~),
// then 8kt x 8nt x (hi+lo) m16n8k8 MMAs per warp.
// ================================================================
__global__ void __launch_bounds__(256, 2) attn_kernel(const int* __restrict__ adj,
                                                      float* __restrict__ out) {
    extern __shared__ float sm[];
    float* psm = sm;                 // [128][68]  34816B
    float* hs  = sm + 128 * 68;      // [2][8192]  65536B
    float* lsm = hs + 2 * 8192;      // [128]      512B

    const int t  = threadIdx.x;
    const int ln = t & 31;
    const int w  = t >> 5;
    const int b  = blockIdx.y;
    const int ib = blockIdx.x * 128;
    const long bn = (long)b * 2048;
    const int R0 = w * 16;           // warp row base

    // score-phase decomposition: rows rh+2i (i=0..7), j's u*4..+3
    const int u  = ln & 15;
    const int rh = ln >> 4;
    // mma-phase decomposition
    const int q  = ln & 3;
    const int r4 = ln >> 2;

    float ssrcv[8];
    #pragma unroll
    for (int i = 0; i < 8; i++)
        ssrcv[i] = g_ssrc[bn + ib + R0 + rh + 2 * i];

    const int*    adjp  = adj + (bn + ib + R0 + rh) * 2048 + u * 4;
    const float4* hsrc4 = (const float4*)(g_hc + (long)b * 32 * 8192);
    const uint    hs_u  = smem_u32(hs);

    float acc[8][4];
    #pragma unroll
    for (int nt = 0; nt < 8; nt++)
        #pragma unroll
        for (int e = 0; e < 4; e++) acc[nt][e] = 0.f;
    float lpart[8];
    #pragma unroll
    for (int i = 0; i < 8; i++) lpart[i] = 0.f;

    // prologue: stream chunk 0 into buf 0
    #pragma unroll
    for (int it = 0; it < 8; it++)
        cpasync16(hs_u + (uint)(t + it * 256) * 16, hsrc4 + t + it * 256);
    asm volatile("cp.async.commit_group;" ::: "memory");

    for (int ck = 0; ck < 32; ck++) {
        const int buf = ck & 1;
        const int jc  = ck * 64;
        __syncthreads();             // prev mma readers of psm/hs[buf^1] done
        if (ck < 31) {               // stream next chunk into the other buffer
            const float4* s = hsrc4 + (ck + 1) * 2048;
            const uint d = hs_u + (uint)(buf ^ 1) * 32768;
            #pragma unroll
            for (int it = 0; it < 8; it++)
                cpasync16(d + (uint)(t + it * 256) * 16, s + t + it * 256);
            asm volatile("cp.async.commit_group;" ::: "memory");
        }

        // ---- score phase (independent of hs) ----
        const float4 sd = *((const float4*)(g_sdst + bn + jc) + u);
        #pragma unroll
        for (int i = 0; i < 8; i++) {
            const int4 a = *(const int4*)(adjp + (long)(2 * i) * 2048 + jc);
            const float p0 = (a.x > 0) ? rna_tf32(__expf(fmaxf(ssrcv[i] + sd.x, 0.f))) : 0.f;
            const float p1 = (a.y > 0) ? rna_tf32(__expf(fmaxf(ssrcv[i] + sd.y, 0.f))) : 0.f;
            const float p2 = (a.z > 0) ? rna_tf32(__expf(fmaxf(ssrcv[i] + sd.z, 0.f))) : 0.f;
            const float p3 = (a.w > 0) ? rna_tf32(__expf(fmaxf(ssrcv[i] + sd.w, 0.f))) : 0.f;
            lpart[i] += (p0 + p1) + (p2 + p3);
            *(float4*)&psm[(R0 + rh + 2 * i) * 68 + u * 4] = make_float4(p0, p1, p2, p3);
        }

        if (ck < 31) asm volatile("cp.async.wait_group 1;" ::: "memory");
        else         asm volatile("cp.async.wait_group 0;" ::: "memory");
        __syncthreads();             // psm + hs[buf] visible

        // ---- mma phase: 8 kt x 8 nt x (hi+lo) ----
        const float* hb = hs + buf * 8192;
        #pragma unroll
        for (int kt = 0; kt < 8; kt++) {
            const int pcol = kt * 8 + q;
            const uint A0 = __float_as_uint(psm[(R0 + r4) * 68 + pcol]);
            const uint A1 = __float_as_uint(psm[(R0 + r4 + 8) * 68 + pcol]);
            const uint A2 = __float_as_uint(psm[(R0 + r4) * 68 + pcol + 4]);
            const uint A3 = __float_as_uint(psm[(R0 + r4 + 8) * 68 + pcol + 4]);
            #pragma unroll
            for (int nt = 0; nt < 8; nt++) {
                const int c = nt * 8 + r4;
                const float4 bq = *(const float4*)&hb[kt * 1024 + c * 16 + q * 4];
                const uint b0h = __float_as_uint(bq.x), b1h = __float_as_uint(bq.y);
                const uint b0l = __float_as_uint(bq.z), b1l = __float_as_uint(bq.w);
                MMA_TF32(acc[nt], A0, A1, A2, A3, b0h, b1h);
                MMA_TF32(acc[nt], A0, A1, A2, A3, b0l, b1l);
            }
        }
    }

    // ---- l: reduce over the 16 u-lanes of each rh half ----
    #pragma unroll
    for (int o = 1; o < 16; o <<= 1)
        #pragma unroll
        for (int i = 0; i < 8; i++)
            lpart[i] += __shfl_xor_sync(0xffffffffu, lpart[i], o);
    if (ln == 0) {
        #pragma unroll
        for (int i = 0; i < 8; i++) lsm[R0 + 2 * i] = lpart[i];
    } else if (ln == 16) {
        #pragma unroll
        for (int i = 0; i < 8; i++) lsm[R0 + 2 * i + 1] = lpart[i];
    }
    __syncwarp();

    // ---- epilogue ----
    const float inv0 = 1.f / lsm[R0 + r4];
    const float inv1 = 1.f / lsm[R0 + r4 + 8];
    const long row0 = bn + ib + R0 + r4;
    #pragma unroll
    for (int nt = 0; nt < 8; nt++) {
        *(float2*)(out + row0 * 64 + nt * 8 + 2 * q) =
            make_float2(acc[nt][0] * inv0, acc[nt][1] * inv0);
        *(float2*)(out + (row0 + 8) * 64 + nt * 8 + 2 * q) =
            make_float2(acc[nt][2] * inv1, acc[nt][3] * inv1);
    }
}

// ================================================================
// launch
// inputs: x f32[16,2048,256], adj i32[16,2048,2048],
//         weight f32[256,64], weight2 f32[128,1]
// output: f32[16,2048,64]
// ================================================================
extern "C" void kernel_launch(void* const* d_in, const int* in_sizes, int n_in,
                              void* d_out, int out_size) {
    const float* x   = (const float*)d_in[0];
    const int*   adj = (const int*)d_in[1];
    const float* W   = (const float*)d_in[2];
    const float* w2  = (const float*)d_in[3];
    float* out = (float*)d_out;

    cudaFuncSetAttribute(gemm_h_kernel,
                         cudaFuncAttributeMaxDynamicSharedMemorySize, 98304);
    cudaFuncSetAttribute(attn_kernel,
                         cudaFuncAttributeMaxDynamicSharedMemorySize, 100864);

    gemm_h_kernel<<<1024, 256, 98304>>>(x, W, w2);       // 32 rows/block
    attn_kernel<<<dim3(16, 16), 256, 100864>>>(adj, out); // 128 rows/CTA
}